// round 8
// baseline (speedup 1.0000x reference)
#include <cuda_runtime.h>

// Problem constants (fixed-shape problem)
#define N_NODES_MAX 30000
#define C_CH 256

typedef unsigned long long ull;

// ---------------- scratch (static __device__, no allocation) ----------------
__device__ float g_h[(size_t)N_NODES_MAX * 512];   // complex linear output: [n][0:256]=re, [256:512]=im
__device__ float g_sums[512];                      // [0:256]=sum(mag), [256:512]=sum(mag^2)
__device__ float g_stats[512];                     // [0:256]=mean, [256:512]=1/(sqrt(var+eps)+eps)

// ---------------- packed f32x2 helpers (Blackwell full-rate FP32) ----------------
__device__ __forceinline__ ull pack_dup(float x) {
    ull r; asm("mov.b64 %0, {%1, %2};" : "=l"(r) : "f"(x), "f"(x)); return r;
}
__device__ __forceinline__ void ffma2(ull &c, ull a, ull b) {
    asm("fma.rn.f32x2 %0, %1, %2, %0;" : "+l"(c) : "l"(a), "l"(b));
}
__device__ __forceinline__ float2 unpack2(ull v) {
    float2 r; asm("mov.b64 {%0, %1}, %2;" : "=f"(r.x), "=f"(r.y) : "l"(v)); return r;
}

// ---------------- Phase A: h = clip(x) @ [wr|wi]^T + [br|bi] ----------------
// C = A(M x 256) * B^T, B rows = concat(w_real, w_imag) (512 x 256), out g_h (M x 512).
// 128x128 block tile, 8x8 per-thread micro-tile, f32x2 packed FMA along N.
__global__ void __launch_bounds__(256, 2)
gemm_kernel(const float* __restrict__ x,
            const float* __restrict__ wr, const float* __restrict__ wi,
            const float* __restrict__ br, const float* __restrict__ bi,
            int M)
{
    __shared__ __align__(16) float As[8][128];
    __shared__ __align__(16) float Bs[8][128];

    const int tid = threadIdx.x;
    const int bm  = blockIdx.x * 128;
    const int by  = blockIdx.y;                   // 0,1 -> w_real ; 2,3 -> w_imag

    const float* Wsrc  = (by < 2) ? wr : wi;
    const float* bsrc  = (by < 2) ? br : bi;
    const int    wrow0 = (by & 1) * 128;

    const int lrow = tid >> 1;                    // 0..127
    const int lkk  = (tid & 1) * 4;               // 0 or 4
    const bool arow_ok = (bm + lrow) < M;
    const float* aptr = x    + (size_t)(bm + lrow) * 256 + lkk;
    const float* bptr = Wsrc + (size_t)(wrow0 + lrow) * 256 + lkk;

    const int tx = tid & 15;                      // N direction (8 cols)
    const int ty = tid >> 4;                      // M direction (8 rows)

    ull acc[8][4];
    #pragma unroll
    for (int i = 0; i < 8; i++)
        #pragma unroll
        for (int j = 0; j < 4; j++) acc[i][j] = 0ULL;

    float4 aReg = make_float4(0.f, 0.f, 0.f, 0.f);
    if (arow_ok) aReg = *(const float4*)aptr;
    float4 bReg = *(const float4*)bptr;

    for (int kt = 0; kt < 256; kt += 8) {
        // store current tile (clip x to [-10,10] as in reference)
        As[lkk + 0][lrow] = fminf(fmaxf(aReg.x, -10.f), 10.f);
        As[lkk + 1][lrow] = fminf(fmaxf(aReg.y, -10.f), 10.f);
        As[lkk + 2][lrow] = fminf(fmaxf(aReg.z, -10.f), 10.f);
        As[lkk + 3][lrow] = fminf(fmaxf(aReg.w, -10.f), 10.f);
        Bs[lkk + 0][lrow] = bReg.x;
        Bs[lkk + 1][lrow] = bReg.y;
        Bs[lkk + 2][lrow] = bReg.z;
        Bs[lkk + 3][lrow] = bReg.w;
        __syncthreads();

        // prefetch next k-tile into registers (overlaps with compute)
        if (kt + 8 < 256) {
            aReg = arow_ok ? *(const float4*)(aptr + kt + 8) : make_float4(0.f, 0.f, 0.f, 0.f);
            bReg = *(const float4*)(bptr + kt + 8);
        }

        #pragma unroll
        for (int k = 0; k < 8; k++) {
            float4 a0 = *(const float4*)&As[k][ty * 8];
            float4 a1 = *(const float4*)&As[k][ty * 8 + 4];
            ulonglong2 bb0 = *(const ulonglong2*)&Bs[k][tx * 8];
            ulonglong2 bb1 = *(const ulonglong2*)&Bs[k][tx * 8 + 4];
            ull b0 = bb0.x, b1 = bb0.y, b2 = bb1.x, b3 = bb1.y;
            float am[8] = {a0.x, a0.y, a0.z, a0.w, a1.x, a1.y, a1.z, a1.w};
            #pragma unroll
            for (int i = 0; i < 8; i++) {
                ull aa = pack_dup(am[i]);
                ffma2(acc[i][0], aa, b0);
                ffma2(acc[i][1], aa, b1);
                ffma2(acc[i][2], aa, b2);
                ffma2(acc[i][3], aa, b3);
            }
        }
        __syncthreads();
    }

    float bias[8];
    #pragma unroll
    for (int j = 0; j < 8; j++) bias[j] = bsrc[wrow0 + tx * 8 + j];

    const int ncol = by * 128 + tx * 8;
    #pragma unroll
    for (int i = 0; i < 8; i++) {
        int m = bm + ty * 8 + i;
        if (m >= M) continue;
        float4 o0, o1; float2 p;
        p = unpack2(acc[i][0]); o0.x = p.x + bias[0]; o0.y = p.y + bias[1];
        p = unpack2(acc[i][1]); o0.z = p.x + bias[2]; o0.w = p.y + bias[3];
        p = unpack2(acc[i][2]); o1.x = p.x + bias[4]; o1.y = p.y + bias[5];
        p = unpack2(acc[i][3]); o1.z = p.x + bias[6]; o1.w = p.y + bias[7];
        float* dst = g_h + (size_t)m * 512 + ncol;
        *(float4*)dst       = o0;
        *(float4*)(dst + 4) = o1;
    }
}

// ---------------- Phase B: per-node unitary row + gather + residual + mag stats ----------------
// U row 0: v = e0 + sum_{k=1..4} term_k with term_k = term_{k-1} @ (-i*Mhat) / k,
// Mhat = H * (1e-4 / ||H||_F). (Eigen/norm clamps provably always trigger -> closed form;
// Taylor-norm clamps and unitarity fallback provably never trigger at ||A||=1e-4.)
//
// Index dtype probe: slot 0 of every subgraph is the center node (sub_nodes[n][0]==n).
// As int32 words: int32 storage => word[8] == sub_nodes[2][0] == 2;
//                 int64 storage => word[8] == low32(sub_nodes[1][0]) == 1.
// So (word[8] == 1) <=> int64. Deterministic, branch computed once.
#define NPB 32
__global__ void __launch_bounds__(256)
evolve_kernel(const float* __restrict__ x,
              const void* __restrict__ sub_nodes_raw,
              const float* __restrict__ sub_mask,
              const float* __restrict__ sub_H,
              const float* __restrict__ es_ptr,
              float* __restrict__ zout,
              int M)
{
    __shared__ float s_wr[NPB][4];
    __shared__ float s_wi[NPB][4];
    __shared__ int   s_idx[NPB][4];

    const int tid  = threadIdx.x;
    const int base = blockIdx.x * NPB;

    const int*       sn32 = (const int*)sub_nodes_raw;
    const long long* sn64 = (const long long*)sub_nodes_raw;
    const bool is64 = (M > 2) ? (sn32[8] == 1) : false;

    if (tid < NPB) {
        int n = base + tid;
        if (n < M) {
            float Mu[16];
            float ss = 0.f;
            #pragma unroll
            for (int i = 0; i < 16; i++) {
                float v = sub_H[(size_t)n * 16 + i];
                Mu[i] = v; ss += v * v;
            }
            float sc = 1e-4f / sqrtf(ss);       // ||H||_F >= ~0.9, never 0
            #pragma unroll
            for (int i = 0; i < 16; i++) Mu[i] *= sc;

            float vr[4] = {1.f, 0.f, 0.f, 0.f}, vi[4] = {0.f, 0.f, 0.f, 0.f};
            float tr[4] = {1.f, 0.f, 0.f, 0.f}, ti[4] = {0.f, 0.f, 0.f, 0.f};
            #pragma unroll
            for (int k = 1; k <= 4; k++) {
                float invk = 1.f / (float)k;
                float ntr[4], nti[4];
                #pragma unroll
                for (int j = 0; j < 4; j++) {
                    float pr = tr[0]*Mu[j] + tr[1]*Mu[4+j] + tr[2]*Mu[8+j] + tr[3]*Mu[12+j];
                    float qr = ti[0]*Mu[j] + ti[1]*Mu[4+j] + ti[2]*Mu[8+j] + ti[3]*Mu[12+j];
                    ntr[j] =  qr * invk;        // (p + iq)(-iM)/k = qM/k - i pM/k
                    nti[j] = -pr * invk;
                }
                #pragma unroll
                for (int j = 0; j < 4; j++) {
                    tr[j] = ntr[j]; ti[j] = nti[j];
                    vr[j] += ntr[j]; vi[j] += nti[j];
                }
            }
            #pragma unroll
            for (int s = 0; s < 4; s++) {
                float mk = sub_mask[(size_t)n * 4 + s];
                s_wr[tid][s]  = vr[s] * mk;
                s_wi[tid][s]  = vi[s] * mk;
                long long raw = is64 ? sn64[(size_t)n * 4 + s]
                                     : (long long)sn32[(size_t)n * 4 + s];
                int j = (int)raw;
                if (j < 0 || j >= M) j = n;     // safety clamp (never hit if inputs sane)
                s_idx[tid][s] = j;
            }
        }
    }
    __syncthreads();

    const int c = tid;                 // one thread per channel
    const float es = *es_ptr;
    float smag = 0.f, smag2 = 0.f;

    for (int l = 0; l < NPB; l++) {
        int n = base + l;
        if (n >= M) break;
        float er = 0.f, ei = 0.f;
        #pragma unroll
        for (int s = 0; s < 4; s++) {
            int   j   = s_idx[l][s];
            float cwr = s_wr[l][s];
            float cwi = s_wi[l][s];
            float hr  = g_h[(size_t)j * 512 + c];
            float hi  = g_h[(size_t)j * 512 + 256 + c];
            er += cwr * hr - cwi * hi;
            ei += cwr * hi + cwi * hr;
        }
        float zr = er * es + x[(size_t)n * 256 + c];   // residual uses UNclipped x
        float zi = ei * es;
        zout[(size_t)n * 512 + c]       = zr;
        zout[(size_t)n * 512 + 256 + c] = zi;
        float mag = sqrtf(zr * zr + zi * zi + 1e-5f);
        mag = fminf(fmaxf(mag, 1e-5f), 1000.f);
        smag  += mag;
        smag2 += mag * mag;
    }
    atomicAdd(&g_sums[c],       smag);
    atomicAdd(&g_sums[256 + c], smag2);
}

// ---------------- Phase C: per-channel mean / inv-std ----------------
__global__ void stats_kernel(float inv_n)
{
    int c = threadIdx.x;   // 256
    float mean = g_sums[c] * inv_n;
    float var  = fmaxf(g_sums[256 + c] * inv_n - mean * mean, 0.f);
    g_stats[c]       = mean;
    g_stats[256 + c] = 1.f / (sqrtf(var + 1e-5f) + 1e-5f);
}

// ---------------- Phase D: layernorm-magnitude + phase + crelu (in-place on d_out) ----------------
__global__ void finalize_kernel(float* __restrict__ z,
                                const float* __restrict__ lnw,
                                const float* __restrict__ lnb,
                                int M)
{
    int n = blockIdx.x;
    int c = threadIdx.x;
    if (n >= M) return;
    size_t i0 = (size_t)n * 512 + c;
    float zr = z[i0];
    float zi = z[i0 + 256];

    float mag = fminf(fmaxf(sqrtf(zr * zr + zi * zi + 1e-5f), 1e-5f), 1000.f);
    float nm  = (mag - g_stats[c]) * g_stats[256 + c];
    float smv = fminf(fmaxf(nm * fabsf(lnw[c]) + lnb[c], 1e-5f), 10.f);

    float re1 = fminf(fmaxf(zr, -1e6f), 1e6f) + 1e-10f;
    float im1 = fminf(fmaxf(zi, -1e6f), 1e6f);
    float r = sqrtf(re1 * re1 + im1 * im1);
    float co, si;
    if (r > 0.f) { co = re1 / r; si = im1 / r; }
    else         { co = 1.f;     si = 0.f;     }   // atan2(0,0) = 0

    float orr = smv * co;
    float oim = smv * si;
    orr = fminf(fmaxf(orr, -5.f), 5.f);
    oim = fminf(fmaxf(oim, -5.f), 5.f);
    orr = (orr > 0.f) ? orr : 0.01f * orr;
    oim = (oim > 0.f) ? oim : 0.01f * oim;

    z[i0]       = orr;
    z[i0 + 256] = oim;
}

__global__ void zero_sums_kernel() { g_sums[threadIdx.x] = 0.f; }

// ---------------- launch ----------------
extern "C" void kernel_launch(void* const* d_in, const int* in_sizes, int n_in,
                              void* d_out, int out_size)
{
    const float* x         = (const float*)d_in[0];
    // d_in[1] = edge_index (unused: subgraph structure is precomputed in sub_*)
    const void*  sub_nodes = d_in[2];               // int32 or int64 — probed in-kernel
    const float* sub_mask  = (const float*)d_in[3];
    const float* sub_H     = (const float*)d_in[4];
    const float* wr        = (const float*)d_in[5];
    const float* wi        = (const float*)d_in[6];
    const float* br        = (const float*)d_in[7];
    const float* bi        = (const float*)d_in[8];
    const float* lnw       = (const float*)d_in[9];
    const float* lnb       = (const float*)d_in[10];
    const float* es        = (const float*)d_in[11];

    int M = in_sizes[0] / C_CH;
    if (M > N_NODES_MAX) M = N_NODES_MAX;
    float* out = (float*)d_out;

    zero_sums_kernel<<<1, 512>>>();

    dim3 ggrid((M + 127) / 128, 4);
    gemm_kernel<<<ggrid, 256>>>(x, wr, wi, br, bi, M);

    evolve_kernel<<<(M + NPB - 1) / NPB, 256>>>(x, sub_nodes, sub_mask, sub_H, es, out, M);

    stats_kernel<<<1, 256>>>(1.f / (float)M);

    finalize_kernel<<<M, 256>>>(out, lnw, lnb, M);
}